// round 11
// baseline (speedup 1.0000x reference)
#include <cuda_runtime.h>
#include <cuda_fp16.h>
#include <cstdint>

// PPO loss + GAE, B=4096 x T=2048 — 3 launches, software-pipelined GAE.
//
//  k1 gae:  one warp per row. Blocked affine suffix scan (CHUNK=8, 256
//           steps per warp scan, 8 segments). SOFTWARE PIPELINE: while
//           scanning segment s, segment s-1's `values` tile is in flight
//           via cp.async (double-buffered, bank-conflict-free padded smem
//           transpose) and s-1's rewards/masks float4s are in flight into
//           registers. The per-warp serial chain drops from
//           8x(mem_lat+scan) to ~mem_lat + 8x(scan). Advantages written
//           fp16 to a 16MB gmem scratch (L2-resident for k2). Exact
//           fp32->double sum(adv), sum(adv^2); value_loss = mean(adv^2).
//  k2 loss: 1,048,576 threads, one 8-elem octet each; mean/rstd derived
//           per block from the k1 accumulators; clipped PPO surrogate
//           (sign-select form) + entropy; block atomics into doubles.
//  k3 fin:  writes the 4 outputs, resets accumulators (replay-safe).

namespace {
constexpr int B = 4096;
constexpr int T = 2048;
constexpr long long NTOT = (long long)B * T;   // 8388608
constexpr float GAMMA = 0.99f;
constexpr float LAM   = 0.95f;
constexpr float GL    = GAMMA * LAM;
constexpr float CLIPP = 0.2f;
constexpr float EPSF  = 1e-9f;

constexpr int CHUNK = 8;                 // timesteps per lane per segment
constexpr int SEG   = 32 * CHUNK;        // 256 timesteps per warp scan
constexpr int NSEG  = T / SEG;           // 8
constexpr int VTILE = 280;               // padded 257 (vpad(256)=264) rounded up
}

__device__ __half g_adv_h[(size_t)B * T];          // 16 MB fp16 adv scratch
__device__ double g_sum, g_sumsq, g_ppo, g_ent;    // zero-init; k3 resets

__device__ __forceinline__ int vpad(int p) { return p + (p >> 5); }

__device__ __forceinline__ void cp_async4(unsigned int dst, const float* src) {
    asm volatile("cp.async.ca.shared.global [%0], [%1], 4;\n"
                 :: "r"(dst), "l"(src));
}
__device__ __forceinline__ void cp_commit() {
    asm volatile("cp.async.commit_group;\n" ::: "memory");
}
template <int N>
__device__ __forceinline__ void cp_wait() {
    asm volatile("cp.async.wait_group %0;\n" :: "n"(N) : "memory");
}

// ---------------------------------------------------------------- k1: GAE
__global__ __launch_bounds__(128) void gae_kernel(
    const float* __restrict__ rewards,
    const float* __restrict__ values,
    const float* __restrict__ masks)
{
    __shared__ float  s_v[4][2][VTILE];   // per-warp double-buffered v tiles
    __shared__ double s_a[4], s_b[4];

    const int tid  = threadIdx.x;
    const int lane = tid & 31;
    const int wid  = tid >> 5;
    const unsigned FULL = 0xffffffffu;

    const int row = blockIdx.x * 4 + wid;          // one warp per row

    const float* rr = rewards + (size_t)row * T;
    const float* vr = values  + (size_t)row * (T + 1);
    const float* mr = masks   + (size_t)row * T;
    __half*      ar = g_adv_h + (size_t)row * T;

    const unsigned int vb0 =
        (unsigned int)__cvta_generic_to_shared(&s_v[wid][0][0]);
    const unsigned int vb1 =
        (unsigned int)__cvta_generic_to_shared(&s_v[wid][1][0]);

    // issue one segment's values tile (coalesced stride-32 lane pattern ->
    // padded transpose tile; write banks (k+lane)%32: conflict-free)
    auto issue_vtile = [&](int seg, unsigned int vb) {
        const int sb = seg * SEG;
        #pragma unroll
        for (int k = 0; k < CHUNK; ++k) {
            const int p = k * 32 + lane;
            cp_async4(vb + 4u * (unsigned int)vpad(p), vr + sb + p);
        }
        if (lane == 0)
            cp_async4(vb + 4u * (unsigned int)vpad(SEG), vr + sb + SEG);
        cp_commit();
    };

    float lsum = 0.f, lsq = 0.f;
    float carry = 0.f;                    // adv[T] = 0

    // ---- prologue: segment NSEG-1 in flight ----
    issue_vtile(NSEG - 1, vb0);
    {
        const int pb = (NSEG - 1) * SEG + lane * CHUNK;
        float4 cra = __ldcs((const float4*)(rr + pb));
        float4 crb = __ldcs((const float4*)(rr + pb) + 1);
        float4 cma = __ldcs((const float4*)(mr + pb));
        float4 cmb = __ldcs((const float4*)(mr + pb) + 1);

        #pragma unroll
        for (int seg = NSEG - 1; seg >= 0; --seg) {
            const int buf  = (NSEG - 1 - seg) & 1;
            const int base = seg * SEG + lane * CHUNK;

            // ---- prefetch segment seg-1 while we compute on seg ----
            float4 nra = cra, nrb = crb, nma = cma, nmb = cmb;
            if (seg > 0) {
                issue_vtile(seg - 1, buf ? vb0 : vb1);
                const int nb = (seg - 1) * SEG + lane * CHUNK;
                nra = __ldcs((const float4*)(rr + nb));
                nrb = __ldcs((const float4*)(rr + nb) + 1);
                nma = __ldcs((const float4*)(mr + nb));
                nmb = __ldcs((const float4*)(mr + nb) + 1);
                cp_wait<1>();             // current tile done; next in flight
            } else {
                cp_wait<0>();
            }
            __syncwarp();                 // all lanes' copies visible

            const float r_[CHUNK] = {cra.x, cra.y, cra.z, cra.w,
                                     crb.x, crb.y, crb.z, crb.w};
            const float m_[CHUNK] = {cma.x, cma.y, cma.z, cma.w,
                                     cmb.x, cmb.y, cmb.z, cmb.w};

            // read transpose tile: addr lane*8 + lane/4 + j -> 32 distinct banks
            const float* vt = &s_v[wid][buf][0];
            float c[CHUNK], d[CHUNK];
            {
                const int rb_ = lane * CHUNK;
                float vj = vt[vpad(rb_)];
                #pragma unroll
                for (int j = 0; j < CHUNK; ++j) {
                    const float vn = vt[vpad(rb_ + j + 1)];
                    c[j] = GL * m_[j];
                    d[j] = fmaf(GAMMA * vn, m_[j], r_[j]) - vj;
                    vj = vn;
                }
            }

            // local suffix composition over this lane's 8 steps
            float C = c[CHUNK - 1], D = d[CHUNK - 1];
            #pragma unroll
            for (int j = CHUNK - 2; j >= 0; --j) {
                D = fmaf(c[j], D, d[j]);
                C = c[j] * C;
            }

            // warp inclusive suffix scan of the 32 per-lane maps
            #pragma unroll
            for (int off = 1; off < 32; off <<= 1) {
                const float C2 = __shfl_down_sync(FULL, C, off);
                const float D2 = __shfl_down_sync(FULL, D, off);
                if (lane + off < 32) {
                    D = fmaf(C, D2, D);
                    C = C * C2;
                }
            }

            const float Cx = __shfl_down_sync(FULL, C, 1);
            const float Dx = __shfl_down_sync(FULL, D, 1);
            float x = (lane == 31) ? carry : fmaf(Cx, carry, Dx);

            float a[CHUNK];
            #pragma unroll
            for (int j = CHUNK - 1; j >= 0; --j) {
                a[j] = fmaf(c[j], x, d[j]);
                x = a[j];
            }
            carry = __shfl_sync(FULL, x, 0);

            // fp16 pack, 16B coalesced store (default policy: stays in L2 for k2)
            const __half2 h0 = __floats2half2_rn(a[0], a[1]);
            const __half2 h1 = __floats2half2_rn(a[2], a[3]);
            const __half2 h2 = __floats2half2_rn(a[4], a[5]);
            const __half2 h3 = __floats2half2_rn(a[6], a[7]);
            uint4 pk;
            pk.x = *(const unsigned int*)&h0;  pk.y = *(const unsigned int*)&h1;
            pk.z = *(const unsigned int*)&h2;  pk.w = *(const unsigned int*)&h3;
            *(uint4*)(ar + base) = pk;

            #pragma unroll
            for (int j = 0; j < CHUNK; ++j) {
                lsum += a[j];
                lsq = fmaf(a[j], a[j], lsq);
            }

            __syncwarp();   // tile[buf] reads done before next iter overwrites it
            cra = nra; crb = nrb; cma = nma; cmb = nmb;
        }
    }

    // CTA reduce of the moments
    #pragma unroll
    for (int off = 16; off; off >>= 1) {
        lsum += __shfl_down_sync(FULL, lsum, off);
        lsq  += __shfl_down_sync(FULL, lsq,  off);
    }
    if (lane == 0) { s_a[wid] = (double)lsum; s_b[wid] = (double)lsq; }
    __syncthreads();
    if (tid == 0) {
        double bs = 0.0, bq = 0.0;
        #pragma unroll
        for (int i = 0; i < 4; ++i) { bs += s_a[i]; bq += s_b[i]; }
        atomicAdd(&g_sum,   bs);
        atomicAdd(&g_sumsq, bq);
    }
}

// ---------------------------------------------------------------- k2: loss
__global__ __launch_bounds__(256) void loss_kernel(
    const float* __restrict__ old_p,
    const float* __restrict__ curr_p)
{
    __shared__ float  sh_mean, sh_rstd;
    __shared__ double s_p[8], s_e[8];

    if (threadIdx.x == 0) {
        const double n    = (double)NTOT;
        const double mean = g_sum / n;
        const double var  = (g_sumsq - g_sum * g_sum / n) / (n - 1.0);  // ddof=1
        sh_mean = (float)mean;
        sh_rstd = (float)(1.0 / (sqrt(var) + (double)EPSF));
    }
    __syncthreads();
    const float mean = sh_mean, rstd = sh_rstd;

    // exactly one 8-element octet per thread: 4096 CTAs x 256 thr x 8 = NTOT
    const size_t base = ((size_t)blockIdx.x * 256 + threadIdx.x) * 8;

    const uint4  hh = *(const uint4*)(g_adv_h + base);      // L2-hot fp16 adv
    const float4 o0 = __ldcs((const float4*)(old_p  + base));
    const float4 o1 = __ldcs((const float4*)(old_p  + base) + 1);
    const float4 q0 = __ldcs((const float4*)(curr_p + base));
    const float4 q1 = __ldcs((const float4*)(curr_p + base) + 1);

    float av[8];
    {
        const float2 f0 = __half22float2(*(const __half2*)&hh.x);
        const float2 f1 = __half22float2(*(const __half2*)&hh.y);
        const float2 f2 = __half22float2(*(const __half2*)&hh.z);
        const float2 f3 = __half22float2(*(const __half2*)&hh.w);
        av[0] = f0.x; av[1] = f0.y; av[2] = f1.x; av[3] = f1.y;
        av[4] = f2.x; av[5] = f2.y; av[6] = f3.x; av[7] = f3.y;
    }
    const float ov[8] = {o0.x, o0.y, o0.z, o0.w, o1.x, o1.y, o1.z, o1.w};
    const float cv[8] = {q0.x, q0.y, q0.z, q0.w, q1.x, q1.y, q1.z, q1.w};

    float ppo = 0.f, ent = 0.f;
    #pragma unroll
    for (int k = 0; k < 8; ++k) {
        const float ratio = __fdividef(cv[k], ov[k] + EPSF);
        const float adv   = (av[k] - mean) * rstd;
        // min(r*adv, clip(r)*adv) = (adv>0 ? min(r,1+c) : max(r,1-c)) * adv
        const float rlo = fminf(ratio, 1.f + CLIPP);
        const float rhi = fmaxf(ratio, 1.f - CLIPP);
        ppo = fmaf((adv > 0.f) ? rlo : rhi, adv, ppo);
        ent = fmaf(cv[k], __logf(cv[k] + EPSF), ent);
    }

    const int lane = threadIdx.x & 31, wid = threadIdx.x >> 5;
    #pragma unroll
    for (int off = 16; off; off >>= 1) {
        ppo += __shfl_down_sync(0xffffffffu, ppo, off);
        ent += __shfl_down_sync(0xffffffffu, ent, off);
    }
    if (lane == 0) { s_p[wid] = (double)ppo; s_e[wid] = (double)ent; }
    __syncthreads();
    if (threadIdx.x == 0) {
        double bp = 0.0, be = 0.0;
        #pragma unroll
        for (int i = 0; i < 8; ++i) { bp += s_p[i]; be += s_e[i]; }
        atomicAdd(&g_ppo, bp);
        atomicAdd(&g_ent, be);
    }
}

// ---------------------------------------------------------------- k3: finalize
__global__ void finalize_kernel(float* __restrict__ out) {
    const double n   = (double)NTOT;
    const double pl  = -(g_ppo / n);
    const double vls = 0.5  * (g_sumsq / n);   // value_loss = mean(adv^2)
    const double el  = -0.01 * (g_ent / n);
    out[0] = (float)(pl + vls + el);
    out[1] = (float)pl;
    out[2] = (float)vls;
    out[3] = (float)el;
    // reset for the next graph replay (deterministic start state)
    g_sum = 0.0; g_sumsq = 0.0; g_ppo = 0.0; g_ent = 0.0;
}

extern "C" void kernel_launch(void* const* d_in, const int* in_sizes, int n_in,
                              void* d_out, int out_size)
{
    // `values` has the unique size B*(T+1); everything else keeps metadata
    // order: rewards, ref_probs (unused), old_probs, curr_probs, masks.
    int vi = 1;
    for (int i = 0; i < n_in; ++i)
        if (in_sizes[i] == B * (T + 1)) { vi = i; break; }

    const float* others[8];
    int k = 0;
    for (int i = 0; i < n_in; ++i)
        if (i != vi) others[k++] = (const float*)d_in[i];

    const float* rewards = others[0];
    const float* old_p   = others[2];
    const float* curr_p  = others[3];
    const float* masks   = others[4];
    const float* values  = (const float*)d_in[vi];

    gae_kernel<<<B / 4, 128>>>(rewards, values, masks);   // 1024 CTAs, 1 warp/row
    loss_kernel<<<(int)(NTOT / 8 / 256), 256>>>(old_p, curr_p);   // 4096 CTAs
    finalize_kernel<<<1, 1>>>((float*)d_out);
}

// round 12
// speedup vs baseline: 1.1844x; 1.1844x over previous
#include <cuda_runtime.h>
#include <cuda_fp16.h>
#include <cstdint>

// PPO loss + GAE, B=4096 x T=2048 — single persistent fused kernel with a
// software-pipelined GAE phase.
//
// Grid = 1024 CTAs x 128 threads, 4 rows per CTA (exactly 4096 rows).
// Residency: smem ~25.5KB -> cap 8 CTAs/SM; regs capped at 73 via
// __launch_bounds__(128,7) (the pipelined GAE compiles to ~64 standalone).
// Wave 1 needs max 7 CTAs/SM, so ALL CTAs are resident -> grid-wide spin
// sync is deadlock-free.
//
// Phase 1: one warp per row. Blocked affine suffix scan (CHUNK=8, 256
//          steps per warp scan, 8 segments) of adv[t]=d[t]+c[t]*adv[t+1].
//          PIPELINE: while scanning segment s, segment s-1's `values`
//          tile is in flight via cp.async (double-buffered padded smem
//          transpose, bank-conflict-free) and s-1's rewards/masks float4s
//          are in flight into registers. Advantages staged in smem fp16
//          (no gmem scratch). Exact fp32->double sum(adv), sum(adv^2);
//          value_loss = mean((returns-values)^2) = mean(adv^2).
// Sync:    atomic arrive + volatile-load spin.
// Phase 2: mean/rstd from global sums; clipped PPO surrogate
//          (sign-select form) + entropy over old/curr with adv from smem.
// Finish:  last CTA writes the 4 outputs and resets all device globals
//          (deterministic across graph replays).
//
// Traffic: 96MB (phase 1) + 64MB (phase 2) = 160MB, adv never touches HBM.

namespace {
constexpr int B = 4096;
constexpr int T = 2048;
constexpr long long NTOT = (long long)B * T;   // 8388608
constexpr float GAMMA = 0.99f;
constexpr float LAM   = 0.95f;
constexpr float GL    = GAMMA * LAM;
constexpr float CLIPP = 0.2f;
constexpr float EPSF  = 1e-9f;

constexpr int CHUNK = 8;                 // timesteps per lane per segment
constexpr int SEG   = 32 * CHUNK;        // 256 timesteps per warp scan
constexpr int NSEG  = T / SEG;           // 8
constexpr int VTILE = 280;               // padded 257 (vpad(256)=264) rounded up

constexpr int GRID  = 1024;              // all resident (7/SM max needed)
constexpr int RPC   = 4;                 // rows per CTA
}

__device__ double g_sum, g_sumsq, g_ppo, g_ent;   // zero-init; reset each replay
__device__ int    g_c1, g_c2;                      // phase counters

__device__ __forceinline__ int vpad(int p) { return p + (p >> 5); }

__device__ __forceinline__ void cp_async4(unsigned int dst, const float* src) {
    asm volatile("cp.async.ca.shared.global [%0], [%1], 4;\n"
                 :: "r"(dst), "l"(src));
}
__device__ __forceinline__ void cp_commit() {
    asm volatile("cp.async.commit_group;\n" ::: "memory");
}
template <int N>
__device__ __forceinline__ void cp_wait() {
    asm volatile("cp.async.wait_group %0;\n" :: "n"(N) : "memory");
}

__global__ __launch_bounds__(128, 7) void ppo_fused_kernel(
    const float* __restrict__ rewards,
    const float* __restrict__ values,
    const float* __restrict__ masks,
    const float* __restrict__ old_p,
    const float* __restrict__ curr_p,
    float* __restrict__ out)
{
    __shared__ __half s_adv[RPC][T];      // 16 KB fp16 advantages
    __shared__ float  s_v[4][2][VTILE];   // 8.75 KB double-buffered v tiles
    __shared__ double s_a[4], s_b[4];
    __shared__ float  sh_mean, sh_rstd;

    const int tid  = threadIdx.x;
    const int lane = tid & 31;
    const int wid  = tid >> 5;
    const unsigned FULL = 0xffffffffu;

    // ========== Phase 1: pipelined GAE -> smem fp16, moment sums ==========
    float lsum = 0.f, lsq = 0.f;

    {
        const int row = blockIdx.x + GRID * wid;   // one warp per row

        const float* rr = rewards + (size_t)row * T;
        const float* vr = values  + (size_t)row * (T + 1);
        const float* mr = masks   + (size_t)row * T;
        __half*      ar = &s_adv[wid][0];

        const unsigned int vb0 =
            (unsigned int)__cvta_generic_to_shared(&s_v[wid][0][0]);
        const unsigned int vb1 =
            (unsigned int)__cvta_generic_to_shared(&s_v[wid][1][0]);

        // issue one segment's values tile (coalesced stride-32 lane loads ->
        // padded transpose tile; write banks (k+lane)%32: conflict-free)
        auto issue_vtile = [&](int seg, unsigned int vb) {
            const int sb = seg * SEG;
            #pragma unroll
            for (int k = 0; k < CHUNK; ++k) {
                const int p = k * 32 + lane;
                cp_async4(vb + 4u * (unsigned int)vpad(p), vr + sb + p);
            }
            if (lane == 0)
                cp_async4(vb + 4u * (unsigned int)vpad(SEG), vr + sb + SEG);
            cp_commit();
        };

        float carry = 0.f;                // adv[T] = 0

        // ---- prologue: segment NSEG-1 in flight ----
        issue_vtile(NSEG - 1, vb0);
        const int pb = (NSEG - 1) * SEG + lane * CHUNK;
        float4 cra = __ldcs((const float4*)(rr + pb));
        float4 crb = __ldcs((const float4*)(rr + pb) + 1);
        float4 cma = __ldcs((const float4*)(mr + pb));
        float4 cmb = __ldcs((const float4*)(mr + pb) + 1);

        #pragma unroll
        for (int seg = NSEG - 1; seg >= 0; --seg) {
            const int buf  = (NSEG - 1 - seg) & 1;
            const int base = seg * SEG + lane * CHUNK;

            // ---- prefetch segment seg-1 while we compute on seg ----
            float4 nra = cra, nrb = crb, nma = cma, nmb = cmb;
            if (seg > 0) {
                issue_vtile(seg - 1, buf ? vb0 : vb1);
                const int nb = (seg - 1) * SEG + lane * CHUNK;
                nra = __ldcs((const float4*)(rr + nb));
                nrb = __ldcs((const float4*)(rr + nb) + 1);
                nma = __ldcs((const float4*)(mr + nb));
                nmb = __ldcs((const float4*)(mr + nb) + 1);
                cp_wait<1>();             // current tile done; next in flight
            } else {
                cp_wait<0>();
            }
            __syncwarp();                 // all lanes' copies visible

            const float r_[CHUNK] = {cra.x, cra.y, cra.z, cra.w,
                                     crb.x, crb.y, crb.z, crb.w};
            const float m_[CHUNK] = {cma.x, cma.y, cma.z, cma.w,
                                     cmb.x, cmb.y, cmb.z, cmb.w};

            // read transpose tile: addr lane*8 + lane/4 + j -> 32 distinct banks
            const float* vt = &s_v[wid][buf][0];
            float c[CHUNK], d[CHUNK];
            {
                const int rb_ = lane * CHUNK;
                float vj = vt[vpad(rb_)];
                #pragma unroll
                for (int j = 0; j < CHUNK; ++j) {
                    const float vn = vt[vpad(rb_ + j + 1)];
                    c[j] = GL * m_[j];
                    d[j] = fmaf(GAMMA * vn, m_[j], r_[j]) - vj;
                    vj = vn;
                }
            }

            // local suffix composition over this lane's 8 steps
            float C = c[CHUNK - 1], D = d[CHUNK - 1];
            #pragma unroll
            for (int j = CHUNK - 2; j >= 0; --j) {
                D = fmaf(c[j], D, d[j]);
                C = c[j] * C;
            }

            // warp inclusive suffix scan of the 32 per-lane maps
            #pragma unroll
            for (int off = 1; off < 32; off <<= 1) {
                const float C2 = __shfl_down_sync(FULL, C, off);
                const float D2 = __shfl_down_sync(FULL, D, off);
                if (lane + off < 32) {
                    D = fmaf(C, D2, D);
                    C = C * C2;
                }
            }

            const float Cx = __shfl_down_sync(FULL, C, 1);
            const float Dx = __shfl_down_sync(FULL, D, 1);
            float x = (lane == 31) ? carry : fmaf(Cx, carry, Dx);

            float a[CHUNK];
            #pragma unroll
            for (int j = CHUNK - 1; j >= 0; --j) {
                a[j] = fmaf(c[j], x, d[j]);
                x = a[j];
            }
            carry = __shfl_sync(FULL, x, 0);

            // fp16 pack, 16B store to smem (lane-consecutive: conflict-free)
            const __half2 h0 = __floats2half2_rn(a[0], a[1]);
            const __half2 h1 = __floats2half2_rn(a[2], a[3]);
            const __half2 h2 = __floats2half2_rn(a[4], a[5]);
            const __half2 h3 = __floats2half2_rn(a[6], a[7]);
            uint4 pk;
            pk.x = *(const unsigned int*)&h0;  pk.y = *(const unsigned int*)&h1;
            pk.z = *(const unsigned int*)&h2;  pk.w = *(const unsigned int*)&h3;
            *(uint4*)(ar + base) = pk;

            #pragma unroll
            for (int j = 0; j < CHUNK; ++j) {
                lsum += a[j];
                lsq = fmaf(a[j], a[j], lsq);
            }

            __syncwarp();   // tile[buf] reads done before next iter overwrites
            cra = nra; crb = nrb; cma = nma; cmb = nmb;
        }
    }

    // CTA reduce of the moments
    #pragma unroll
    for (int off = 16; off; off >>= 1) {
        lsum += __shfl_down_sync(FULL, lsum, off);
        lsq  += __shfl_down_sync(FULL, lsq,  off);
    }
    if (lane == 0) { s_a[wid] = (double)lsum; s_b[wid] = (double)lsq; }
    __syncthreads();
    if (tid == 0) {
        double bs = 0.0, bq = 0.0;
        #pragma unroll
        for (int i = 0; i < 4; ++i) { bs += s_a[i]; bq += s_b[i]; }
        atomicAdd(&g_sum,   bs);
        atomicAdd(&g_sumsq, bq);
        __threadfence();
        atomicAdd(&g_c1, 1);
        // volatile-load spin; all CTAs resident: safe
        while (*(volatile int*)&g_c1 < GRID) __nanosleep(32);
        const double n    = (double)NTOT;
        const double mean = g_sum / n;
        const double var  = (g_sumsq - g_sum * g_sum / n) / (n - 1.0);  // ddof=1
        sh_mean = (float)mean;
        sh_rstd = (float)(1.0 / (sqrt(var) + (double)EPSF));
    }
    __syncthreads();

    // ========== Phase 2: PPO surrogate + entropy ==========
    const float mean = sh_mean, rstd = sh_rstd;
    float ppo = 0.f, ent = 0.f;

    #pragma unroll
    for (int i = 0; i < RPC; ++i) {
        const int row = blockIdx.x + GRID * i;

        const float4* o4 = (const float4*)(old_p  + (size_t)row * T);
        const float4* c4 = (const float4*)(curr_p + (size_t)row * T);
        const __half* ar = &s_adv[i][0];

        #pragma unroll
        for (int cch = 0; cch < 4; ++cch) {
            const int idx = cch * 128 + tid;     // float4 index within row
            const float4 o  = __ldcs(o4 + idx);
            const float4 cc = __ldcs(c4 + idx);
            const uint2 hh = *(const uint2*)(ar + idx * 4);
            const float2 fa = __half22float2(*(const __half2*)&hh.x);
            const float2 fb = __half22float2(*(const __half2*)&hh.y);

            const float av[4] = {fa.x, fa.y, fb.x, fb.y};
            const float* ov = (const float*)&o;
            const float* cv = (const float*)&cc;
            #pragma unroll
            for (int k = 0; k < 4; ++k) {
                const float ratio = __fdividef(cv[k], ov[k] + EPSF);
                const float adv   = (av[k] - mean) * rstd;
                // min(r*adv, clip(r)*adv) = (adv>0 ? min(r,1+c) : max(r,1-c))*adv
                const float rlo = fminf(ratio, 1.f + CLIPP);
                const float rhi = fmaxf(ratio, 1.f - CLIPP);
                ppo = fmaf((adv > 0.f) ? rlo : rhi, adv, ppo);
                ent = fmaf(cv[k], __logf(cv[k] + EPSF), ent);
            }
        }
    }

    #pragma unroll
    for (int off = 16; off; off >>= 1) {
        ppo += __shfl_down_sync(FULL, ppo, off);
        ent += __shfl_down_sync(FULL, ent, off);
    }
    __syncthreads();   // s_a/s_b reuse
    if (lane == 0) { s_a[wid] = (double)ppo; s_b[wid] = (double)ent; }
    __syncthreads();

    if (tid == 0) {
        double bp = 0.0, be = 0.0;
        #pragma unroll
        for (int i = 0; i < 4; ++i) { bp += s_a[i]; be += s_b[i]; }
        atomicAdd(&g_ppo, bp);
        atomicAdd(&g_ent, be);
        __threadfence();
        const int done = atomicAdd(&g_c2, 1);
        if (done == GRID - 1) {
            // last CTA: finalize output, reset state for the next replay
            const double n   = (double)NTOT;
            const double pl  = -(g_ppo / n);
            const double vls = 0.5  * (g_sumsq / n);   // value_loss = mean(adv^2)
            const double el  = -0.01 * (g_ent / n);
            out[0] = (float)(pl + vls + el);
            out[1] = (float)pl;
            out[2] = (float)vls;
            out[3] = (float)el;
            g_sum = 0.0; g_sumsq = 0.0; g_ppo = 0.0; g_ent = 0.0;
            g_c1 = 0; g_c2 = 0;
            __threadfence();
        }
    }
}

extern "C" void kernel_launch(void* const* d_in, const int* in_sizes, int n_in,
                              void* d_out, int out_size)
{
    // `values` has the unique size B*(T+1); everything else keeps metadata
    // order: rewards, ref_probs (unused), old_probs, curr_probs, masks.
    int vi = 1;
    for (int i = 0; i < n_in; ++i)
        if (in_sizes[i] == B * (T + 1)) { vi = i; break; }

    const float* others[8];
    int k = 0;
    for (int i = 0; i < n_in; ++i)
        if (i != vi) others[k++] = (const float*)d_in[i];

    const float* rewards = others[0];
    const float* old_p   = others[2];
    const float* curr_p  = others[3];
    const float* masks   = others[4];
    const float* values  = (const float*)d_in[vi];

    ppo_fused_kernel<<<GRID, 128>>>(rewards, values, masks, old_p, curr_p,
                                    (float*)d_out);
}

// round 13
// speedup vs baseline: 1.2836x; 1.0838x over previous
#include <cuda_runtime.h>
#include <cuda_fp16.h>
#include <cstdint>

// PPO loss + GAE, B=4096 x T=2048 — single persistent fused kernel,
// software-pipelined GAE + cross-barrier hoisted loss loads.
//
// Grid = 1024 CTAs x 128 threads, 4 rows per CTA. All CTAs resident
// (smem ~25.5KB -> 8 CTAs/SM cap, need 7; regs capped 73 via
// __launch_bounds__(128,7)) -> grid-wide spin sync is deadlock-free.
//
// Phase 1:  one warp per row. Blocked affine suffix scan (CHUNK=8) with a
//           cp.async double-buffered `values` transpose tile and register
//           prefetch of rewards/masks. adv staged in smem fp16.
//           sum(adv), sum(adv^2) in doubles; value_loss = mean(adv^2).
// Arrive:   thread 0 atomics + counter arrive (NO spin yet).
// Phase 2a: PRE-BARRIER: each thread loads half its old/curr elements,
//           computes entropy and caches 32 fp32 ratios in registers
//           (ratio & entropy are mean-independent). Overlaps 32MB of loss
//           traffic with other CTAs' phase-1 tails and the barrier wait.
// Spin:     thread 0 waits for all arrivals, derives mean/rstd (ddof=1).
// Phase 2b: cached elements: ppo from reg ratios + smem adv (no memory).
// Phase 2c: remaining 32 elements: load + ratio + entropy + ppo.
// Finish:   last CTA writes 4 outputs, resets globals (replay-safe).

namespace {
constexpr int B = 4096;
constexpr int T = 2048;
constexpr long long NTOT = (long long)B * T;   // 8388608
constexpr float GAMMA = 0.99f;
constexpr float LAM   = 0.95f;
constexpr float GL    = GAMMA * LAM;
constexpr float CLIPP = 0.2f;
constexpr float EPSF  = 1e-9f;

constexpr int CHUNK = 8;                 // timesteps per lane per segment
constexpr int SEG   = 32 * CHUNK;        // 256 timesteps per warp scan
constexpr int NSEG  = T / SEG;           // 8
constexpr int VTILE = 280;               // padded 257 (vpad(256)=264) rounded up

constexpr int GRID  = 1024;              // all resident (7/SM max needed)
constexpr int RPC   = 4;                 // rows per CTA
}

__device__ double g_sum, g_sumsq, g_ppo, g_ent;   // zero-init; reset each replay
__device__ int    g_c1, g_c2;                      // phase counters

__device__ __forceinline__ int vpad(int p) { return p + (p >> 5); }

__device__ __forceinline__ void cp_async4(unsigned int dst, const float* src) {
    asm volatile("cp.async.ca.shared.global [%0], [%1], 4;\n"
                 :: "r"(dst), "l"(src));
}
__device__ __forceinline__ void cp_commit() {
    asm volatile("cp.async.commit_group;\n" ::: "memory");
}
template <int N>
__device__ __forceinline__ void cp_wait() {
    asm volatile("cp.async.wait_group %0;\n" :: "n"(N) : "memory");
}

__global__ __launch_bounds__(128, 7) void ppo_fused_kernel(
    const float* __restrict__ rewards,
    const float* __restrict__ values,
    const float* __restrict__ masks,
    const float* __restrict__ old_p,
    const float* __restrict__ curr_p,
    float* __restrict__ out)
{
    __shared__ __half s_adv[RPC][T];      // 16 KB fp16 advantages
    __shared__ float  s_v[4][2][VTILE];   // 8.75 KB double-buffered v tiles
    __shared__ double s_a[4], s_b[4];
    __shared__ float  sh_mean, sh_rstd;

    const int tid  = threadIdx.x;
    const int lane = tid & 31;
    const int wid  = tid >> 5;
    const unsigned FULL = 0xffffffffu;

    // ========== Phase 1: pipelined GAE -> smem fp16, moment sums ==========
    float lsum = 0.f, lsq = 0.f;

    {
        const int row = blockIdx.x + GRID * wid;   // one warp per row

        const float* rr = rewards + (size_t)row * T;
        const float* vr = values  + (size_t)row * (T + 1);
        const float* mr = masks   + (size_t)row * T;
        __half*      ar = &s_adv[wid][0];

        const unsigned int vb0 =
            (unsigned int)__cvta_generic_to_shared(&s_v[wid][0][0]);
        const unsigned int vb1 =
            (unsigned int)__cvta_generic_to_shared(&s_v[wid][1][0]);

        auto issue_vtile = [&](int seg, unsigned int vb) {
            const int sb = seg * SEG;
            #pragma unroll
            for (int k = 0; k < CHUNK; ++k) {
                const int p = k * 32 + lane;
                cp_async4(vb + 4u * (unsigned int)vpad(p), vr + sb + p);
            }
            if (lane == 0)
                cp_async4(vb + 4u * (unsigned int)vpad(SEG), vr + sb + SEG);
            cp_commit();
        };

        float carry = 0.f;                // adv[T] = 0

        issue_vtile(NSEG - 1, vb0);
        const int pb = (NSEG - 1) * SEG + lane * CHUNK;
        float4 cra = __ldcs((const float4*)(rr + pb));
        float4 crb = __ldcs((const float4*)(rr + pb) + 1);
        float4 cma = __ldcs((const float4*)(mr + pb));
        float4 cmb = __ldcs((const float4*)(mr + pb) + 1);

        #pragma unroll
        for (int seg = NSEG - 1; seg >= 0; --seg) {
            const int buf  = (NSEG - 1 - seg) & 1;
            const int base = seg * SEG + lane * CHUNK;

            float4 nra = cra, nrb = crb, nma = cma, nmb = cmb;
            if (seg > 0) {
                issue_vtile(seg - 1, buf ? vb0 : vb1);
                const int nb = (seg - 1) * SEG + lane * CHUNK;
                nra = __ldcs((const float4*)(rr + nb));
                nrb = __ldcs((const float4*)(rr + nb) + 1);
                nma = __ldcs((const float4*)(mr + nb));
                nmb = __ldcs((const float4*)(mr + nb) + 1);
                cp_wait<1>();
            } else {
                cp_wait<0>();
            }
            __syncwarp();

            const float r_[CHUNK] = {cra.x, cra.y, cra.z, cra.w,
                                     crb.x, crb.y, crb.z, crb.w};
            const float m_[CHUNK] = {cma.x, cma.y, cma.z, cma.w,
                                     cmb.x, cmb.y, cmb.z, cmb.w};

            const float* vt = &s_v[wid][buf][0];
            float c[CHUNK], d[CHUNK];
            {
                const int rb_ = lane * CHUNK;
                float vj = vt[vpad(rb_)];
                #pragma unroll
                for (int j = 0; j < CHUNK; ++j) {
                    const float vn = vt[vpad(rb_ + j + 1)];
                    c[j] = GL * m_[j];
                    d[j] = fmaf(GAMMA * vn, m_[j], r_[j]) - vj;
                    vj = vn;
                }
            }

            float C = c[CHUNK - 1], D = d[CHUNK - 1];
            #pragma unroll
            for (int j = CHUNK - 2; j >= 0; --j) {
                D = fmaf(c[j], D, d[j]);
                C = c[j] * C;
            }

            #pragma unroll
            for (int off = 1; off < 32; off <<= 1) {
                const float C2 = __shfl_down_sync(FULL, C, off);
                const float D2 = __shfl_down_sync(FULL, D, off);
                if (lane + off < 32) {
                    D = fmaf(C, D2, D);
                    C = C * C2;
                }
            }

            const float Cx = __shfl_down_sync(FULL, C, 1);
            const float Dx = __shfl_down_sync(FULL, D, 1);
            float x = (lane == 31) ? carry : fmaf(Cx, carry, Dx);

            float a[CHUNK];
            #pragma unroll
            for (int j = CHUNK - 1; j >= 0; --j) {
                a[j] = fmaf(c[j], x, d[j]);
                x = a[j];
            }
            carry = __shfl_sync(FULL, x, 0);

            const __half2 h0 = __floats2half2_rn(a[0], a[1]);
            const __half2 h1 = __floats2half2_rn(a[2], a[3]);
            const __half2 h2 = __floats2half2_rn(a[4], a[5]);
            const __half2 h3 = __floats2half2_rn(a[6], a[7]);
            uint4 pk;
            pk.x = *(const unsigned int*)&h0;  pk.y = *(const unsigned int*)&h1;
            pk.z = *(const unsigned int*)&h2;  pk.w = *(const unsigned int*)&h3;
            *(uint4*)(ar + base) = pk;

            #pragma unroll
            for (int j = 0; j < CHUNK; ++j) {
                lsum += a[j];
                lsq = fmaf(a[j], a[j], lsq);
            }

            __syncwarp();
            cra = nra; crb = nrb; cma = nma; cmb = nmb;
        }
    }

    // CTA reduce of the moments + barrier ARRIVE (no spin yet)
    #pragma unroll
    for (int off = 16; off; off >>= 1) {
        lsum += __shfl_down_sync(FULL, lsum, off);
        lsq  += __shfl_down_sync(FULL, lsq,  off);
    }
    if (lane == 0) { s_a[wid] = (double)lsum; s_b[wid] = (double)lsq; }
    __syncthreads();
    if (tid == 0) {
        double bs = 0.0, bq = 0.0;
        #pragma unroll
        for (int i = 0; i < 4; ++i) { bs += s_a[i]; bq += s_b[i]; }
        atomicAdd(&g_sum,   bs);
        atomicAdd(&g_sumsq, bq);
        __threadfence();
        atomicAdd(&g_c1, 1);
    }

    // ========== Phase 2a: PRE-BARRIER loads + entropy + ratio cache ==========
    // Cache chunks 0..1 of each row (32 of this thread's 64 elements).
    float rcache[RPC * 2 * 4];
    float ppo = 0.f, ent = 0.f;

    #pragma unroll
    for (int i = 0; i < RPC; ++i) {
        const int row = blockIdx.x + GRID * i;
        const float4* o4 = (const float4*)(old_p  + (size_t)row * T);
        const float4* c4 = (const float4*)(curr_p + (size_t)row * T);
        #pragma unroll
        for (int cch = 0; cch < 2; ++cch) {
            const int idx = cch * 128 + tid;
            const float4 o  = __ldcs(o4 + idx);
            const float4 cc = __ldcs(c4 + idx);
            const float* ov = (const float*)&o;
            const float* cv = (const float*)&cc;
            #pragma unroll
            for (int k = 0; k < 4; ++k) {
                rcache[(i * 2 + cch) * 4 + k] = __fdividef(cv[k], ov[k] + EPSF);
                ent = fmaf(cv[k], __logf(cv[k] + EPSF), ent);
            }
        }
    }

    // ========== Spin: wait for all arrivals, derive mean/rstd ==========
    if (tid == 0) {
        while (*(volatile int*)&g_c1 < GRID) __nanosleep(32);
        const double n    = (double)NTOT;
        const double mean = g_sum / n;
        const double var  = (g_sumsq - g_sum * g_sum / n) / (n - 1.0);  // ddof=1
        sh_mean = (float)mean;
        sh_rstd = (float)(1.0 / (sqrt(var) + (double)EPSF));
    }
    __syncthreads();
    const float mean = sh_mean, rstd = sh_rstd;

    // ========== Phase 2b: cached elements (no memory traffic) ==========
    #pragma unroll
    for (int i = 0; i < RPC; ++i) {
        const __half* ar = &s_adv[i][0];
        #pragma unroll
        for (int cch = 0; cch < 2; ++cch) {
            const int idx = cch * 128 + tid;
            const uint2 hh = *(const uint2*)(ar + idx * 4);
            const float2 fa = __half22float2(*(const __half2*)&hh.x);
            const float2 fb = __half22float2(*(const __half2*)&hh.y);
            const float av[4] = {fa.x, fa.y, fb.x, fb.y};
            #pragma unroll
            for (int k = 0; k < 4; ++k) {
                const float ratio = rcache[(i * 2 + cch) * 4 + k];
                const float adv   = (av[k] - mean) * rstd;
                const float rlo = fminf(ratio, 1.f + CLIPP);
                const float rhi = fmaxf(ratio, 1.f - CLIPP);
                ppo = fmaf((adv > 0.f) ? rlo : rhi, adv, ppo);
            }
        }
    }

    // ========== Phase 2c: remaining elements (chunks 2..3) ==========
    #pragma unroll
    for (int i = 0; i < RPC; ++i) {
        const int row = blockIdx.x + GRID * i;
        const float4* o4 = (const float4*)(old_p  + (size_t)row * T);
        const float4* c4 = (const float4*)(curr_p + (size_t)row * T);
        const __half* ar = &s_adv[i][0];
        #pragma unroll
        for (int cch = 2; cch < 4; ++cch) {
            const int idx = cch * 128 + tid;
            const float4 o  = __ldcs(o4 + idx);
            const float4 cc = __ldcs(c4 + idx);
            const uint2 hh = *(const uint2*)(ar + idx * 4);
            const float2 fa = __half22float2(*(const __half2*)&hh.x);
            const float2 fb = __half22float2(*(const __half2*)&hh.y);
            const float av[4] = {fa.x, fa.y, fb.x, fb.y};
            const float* ov = (const float*)&o;
            const float* cv = (const float*)&cc;
            #pragma unroll
            for (int k = 0; k < 4; ++k) {
                const float ratio = __fdividef(cv[k], ov[k] + EPSF);
                const float adv   = (av[k] - mean) * rstd;
                const float rlo = fminf(ratio, 1.f + CLIPP);
                const float rhi = fmaxf(ratio, 1.f - CLIPP);
                ppo = fmaf((adv > 0.f) ? rlo : rhi, adv, ppo);
                ent = fmaf(cv[k], __logf(cv[k] + EPSF), ent);
            }
        }
    }

    // ========== Reduce + finalize ==========
    #pragma unroll
    for (int off = 16; off; off >>= 1) {
        ppo += __shfl_down_sync(FULL, ppo, off);
        ent += __shfl_down_sync(FULL, ent, off);
    }
    __syncthreads();   // s_a/s_b reuse
    if (lane == 0) { s_a[wid] = (double)ppo; s_b[wid] = (double)ent; }
    __syncthreads();

    if (tid == 0) {
        double bp = 0.0, be = 0.0;
        #pragma unroll
        for (int i = 0; i < 4; ++i) { bp += s_a[i]; be += s_b[i]; }
        atomicAdd(&g_ppo, bp);
        atomicAdd(&g_ent, be);
        __threadfence();
        const int done = atomicAdd(&g_c2, 1);
        if (done == GRID - 1) {
            const double n   = (double)NTOT;
            const double pl  = -(g_ppo / n);
            const double vls = 0.5  * (g_sumsq / n);   // value_loss = mean(adv^2)
            const double el  = -0.01 * (g_ent / n);
            out[0] = (float)(pl + vls + el);
            out[1] = (float)pl;
            out[2] = (float)vls;
            out[3] = (float)el;
            g_sum = 0.0; g_sumsq = 0.0; g_ppo = 0.0; g_ent = 0.0;
            g_c1 = 0; g_c2 = 0;
            __threadfence();
        }
    }
}

extern "C" void kernel_launch(void* const* d_in, const int* in_sizes, int n_in,
                              void* d_out, int out_size)
{
    // `values` has the unique size B*(T+1); everything else keeps metadata
    // order: rewards, ref_probs (unused), old_probs, curr_probs, masks.
    int vi = 1;
    for (int i = 0; i < n_in; ++i)
        if (in_sizes[i] == B * (T + 1)) { vi = i; break; }

    const float* others[8];
    int k = 0;
    for (int i = 0; i < n_in; ++i)
        if (i != vi) others[k++] = (const float*)d_in[i];

    const float* rewards = others[0];
    const float* old_p   = others[2];
    const float* curr_p  = others[3];
    const float* masks   = others[4];
    const float* values  = (const float*)d_in[vi];

    ppo_fused_kernel<<<GRID, 128>>>(rewards, values, masks, old_p, curr_p,
                                    (float*)d_out);
}

// round 14
// speedup vs baseline: 1.3494x; 1.0512x over previous
#include <cuda_runtime.h>
#include <cuda_fp16.h>
#include <cstdint>

// PPO loss + GAE, B=4096 x T=2048 — single persistent fused kernel,
// software-pipelined GAE + cross-barrier hoisted loss phase (75% hoisted).
//
// Grid = 1024 CTAs x 128 threads, 4 rows per CTA. All CTAs resident
// (smem ~25.5KB -> 8 CTAs/SM cap, need 7; regs capped 73 via
// __launch_bounds__(128,7)) -> grid-wide spin sync is deadlock-free.
//
// Phase 1:  one warp per row. Blocked affine suffix scan (CHUNK=8) with a
//           cp.async double-buffered `values` transpose tile and register
//           prefetch of rewards/masks. adv staged in smem fp16.
//           sum(adv), sum(adv^2) in doubles; value_loss = mean(adv^2).
// Arrive:   thread 0 atomics + counter arrive (NO spin yet).
// Phase 2a: PRE-BARRIER: loads + entropy + ratio for 48 of 64 elements:
//           32 ratios cached in registers, 16 in the now-dead v-tile smem
//           (ratio & entropy are mean-independent). Overlaps 48MB of the
//           64MB loss traffic with phase-1 stragglers and the spin.
// Spin:     thread 0 waits for all arrivals, derives mean/rstd (ddof=1).
// Phase 2b: cached elements: ppo from reg/smem ratios + smem adv.
// Phase 2c: last 16 elements: load + ratio + entropy + ppo (16MB only).
// Finish:   last CTA writes 4 outputs, resets globals (replay-safe).

namespace {
constexpr int B = 4096;
constexpr int T = 2048;
constexpr long long NTOT = (long long)B * T;   // 8388608
constexpr float GAMMA = 0.99f;
constexpr float LAM   = 0.95f;
constexpr float GL    = GAMMA * LAM;
constexpr float CLIPP = 0.2f;
constexpr float EPSF  = 1e-9f;

constexpr int CHUNK = 8;                 // timesteps per lane per segment
constexpr int SEG   = 32 * CHUNK;        // 256 timesteps per warp scan
constexpr int NSEG  = T / SEG;           // 8
constexpr int VTILE = 280;               // padded 257 (vpad(256)=264) rounded up

constexpr int GRID  = 1024;              // all resident (7/SM max needed)
constexpr int RPC   = 4;                 // rows per CTA
}

__device__ double g_sum, g_sumsq, g_ppo, g_ent;   // zero-init; reset each replay
__device__ int    g_c1, g_c2;                      // phase counters

__device__ __forceinline__ int vpad(int p) { return p + (p >> 5); }

__device__ __forceinline__ void cp_async4(unsigned int dst, const float* src) {
    asm volatile("cp.async.ca.shared.global [%0], [%1], 4;\n"
                 :: "r"(dst), "l"(src));
}
__device__ __forceinline__ void cp_commit() {
    asm volatile("cp.async.commit_group;\n" ::: "memory");
}
template <int N>
__device__ __forceinline__ void cp_wait() {
    asm volatile("cp.async.wait_group %0;\n" :: "n"(N) : "memory");
}

__global__ __launch_bounds__(128, 7) void ppo_fused_kernel(
    const float* __restrict__ rewards,
    const float* __restrict__ values,
    const float* __restrict__ masks,
    const float* __restrict__ old_p,
    const float* __restrict__ curr_p,
    float* __restrict__ out)
{
    __shared__ __half s_adv[RPC][T];      // 16 KB fp16 advantages
    __shared__ float  s_v[4][2][VTILE];   // 8.96 KB v tiles; reused as ratio cache
    __shared__ double s_a[4], s_b[4];
    __shared__ float  sh_mean, sh_rstd;

    float* s_rc = &s_v[0][0][0];          // 2240 floats; need 16*128 = 2048

    const int tid  = threadIdx.x;
    const int lane = tid & 31;
    const int wid  = tid >> 5;
    const unsigned FULL = 0xffffffffu;

    // ========== Phase 1: pipelined GAE -> smem fp16, moment sums ==========
    float lsum = 0.f, lsq = 0.f;

    {
        const int row = blockIdx.x + GRID * wid;   // one warp per row

        const float* rr = rewards + (size_t)row * T;
        const float* vr = values  + (size_t)row * (T + 1);
        const float* mr = masks   + (size_t)row * T;
        __half*      ar = &s_adv[wid][0];

        const unsigned int vb0 =
            (unsigned int)__cvta_generic_to_shared(&s_v[wid][0][0]);
        const unsigned int vb1 =
            (unsigned int)__cvta_generic_to_shared(&s_v[wid][1][0]);

        auto issue_vtile = [&](int seg, unsigned int vb) {
            const int sb = seg * SEG;
            #pragma unroll
            for (int k = 0; k < CHUNK; ++k) {
                const int p = k * 32 + lane;
                cp_async4(vb + 4u * (unsigned int)vpad(p), vr + sb + p);
            }
            if (lane == 0)
                cp_async4(vb + 4u * (unsigned int)vpad(SEG), vr + sb + SEG);
            cp_commit();
        };

        float carry = 0.f;                // adv[T] = 0

        issue_vtile(NSEG - 1, vb0);
        const int pb = (NSEG - 1) * SEG + lane * CHUNK;
        float4 cra = __ldcs((const float4*)(rr + pb));
        float4 crb = __ldcs((const float4*)(rr + pb) + 1);
        float4 cma = __ldcs((const float4*)(mr + pb));
        float4 cmb = __ldcs((const float4*)(mr + pb) + 1);

        #pragma unroll
        for (int seg = NSEG - 1; seg >= 0; --seg) {
            const int buf  = (NSEG - 1 - seg) & 1;
            const int base = seg * SEG + lane * CHUNK;

            float4 nra = cra, nrb = crb, nma = cma, nmb = cmb;
            if (seg > 0) {
                issue_vtile(seg - 1, buf ? vb0 : vb1);
                const int nb = (seg - 1) * SEG + lane * CHUNK;
                nra = __ldcs((const float4*)(rr + nb));
                nrb = __ldcs((const float4*)(rr + nb) + 1);
                nma = __ldcs((const float4*)(mr + nb));
                nmb = __ldcs((const float4*)(mr + nb) + 1);
                cp_wait<1>();
            } else {
                cp_wait<0>();
            }
            __syncwarp();

            const float r_[CHUNK] = {cra.x, cra.y, cra.z, cra.w,
                                     crb.x, crb.y, crb.z, crb.w};
            const float m_[CHUNK] = {cma.x, cma.y, cma.z, cma.w,
                                     cmb.x, cmb.y, cmb.z, cmb.w};

            const float* vt = &s_v[wid][buf][0];
            float c[CHUNK], d[CHUNK];
            {
                const int rb_ = lane * CHUNK;
                float vj = vt[vpad(rb_)];
                #pragma unroll
                for (int j = 0; j < CHUNK; ++j) {
                    const float vn = vt[vpad(rb_ + j + 1)];
                    c[j] = GL * m_[j];
                    d[j] = fmaf(GAMMA * vn, m_[j], r_[j]) - vj;
                    vj = vn;
                }
            }

            float C = c[CHUNK - 1], D = d[CHUNK - 1];
            #pragma unroll
            for (int j = CHUNK - 2; j >= 0; --j) {
                D = fmaf(c[j], D, d[j]);
                C = c[j] * C;
            }

            #pragma unroll
            for (int off = 1; off < 32; off <<= 1) {
                const float C2 = __shfl_down_sync(FULL, C, off);
                const float D2 = __shfl_down_sync(FULL, D, off);
                if (lane + off < 32) {
                    D = fmaf(C, D2, D);
                    C = C * C2;
                }
            }

            const float Cx = __shfl_down_sync(FULL, C, 1);
            const float Dx = __shfl_down_sync(FULL, D, 1);
            float x = (lane == 31) ? carry : fmaf(Cx, carry, Dx);

            float a[CHUNK];
            #pragma unroll
            for (int j = CHUNK - 1; j >= 0; --j) {
                a[j] = fmaf(c[j], x, d[j]);
                x = a[j];
            }
            carry = __shfl_sync(FULL, x, 0);

            const __half2 h0 = __floats2half2_rn(a[0], a[1]);
            const __half2 h1 = __floats2half2_rn(a[2], a[3]);
            const __half2 h2 = __floats2half2_rn(a[4], a[5]);
            const __half2 h3 = __floats2half2_rn(a[6], a[7]);
            uint4 pk;
            pk.x = *(const unsigned int*)&h0;  pk.y = *(const unsigned int*)&h1;
            pk.z = *(const unsigned int*)&h2;  pk.w = *(const unsigned int*)&h3;
            *(uint4*)(ar + base) = pk;

            #pragma unroll
            for (int j = 0; j < CHUNK; ++j) {
                lsum += a[j];
                lsq = fmaf(a[j], a[j], lsq);
            }

            __syncwarp();
            cra = nra; crb = nrb; cma = nma; cmb = nmb;
        }
    }

    // CTA reduce of the moments + barrier ARRIVE (no spin yet)
    #pragma unroll
    for (int off = 16; off; off >>= 1) {
        lsum += __shfl_down_sync(FULL, lsum, off);
        lsq  += __shfl_down_sync(FULL, lsq,  off);
    }
    if (lane == 0) { s_a[wid] = (double)lsum; s_b[wid] = (double)lsq; }
    __syncthreads();   // also: all v-tile reads complete -> s_rc reuse is safe
    if (tid == 0) {
        double bs = 0.0, bq = 0.0;
        #pragma unroll
        for (int i = 0; i < 4; ++i) { bs += s_a[i]; bq += s_b[i]; }
        atomicAdd(&g_sum,   bs);
        atomicAdd(&g_sumsq, bq);
        __threadfence();
        atomicAdd(&g_c1, 1);
    }

    // ========== Phase 2a: PRE-BARRIER loads + entropy + ratio caches ==========
    float rcache[RPC * 2 * 4];   // rows 0..3, chunks 0..1 -> registers
    float ppo = 0.f, ent = 0.f;

    #pragma unroll
    for (int i = 0; i < RPC; ++i) {
        const int row = blockIdx.x + GRID * i;
        const float4* o4 = (const float4*)(old_p  + (size_t)row * T);
        const float4* c4 = (const float4*)(curr_p + (size_t)row * T);
        #pragma unroll
        for (int cch = 0; cch < 2; ++cch) {
            const int idx = cch * 128 + tid;
            const float4 o  = __ldcs(o4 + idx);
            const float4 cc = __ldcs(c4 + idx);
            const float* ov = (const float*)&o;
            const float* cv = (const float*)&cc;
            #pragma unroll
            for (int k = 0; k < 4; ++k) {
                rcache[(i * 2 + cch) * 4 + k] = __fdividef(cv[k], ov[k] + EPSF);
                ent = fmaf(cv[k], __logf(cv[k] + EPSF), ent);
            }
        }
    }
    // rows 0..1, chunks 2..3 -> smem ratio cache (stride-1 across threads)
    #pragma unroll
    for (int i = 0; i < 2; ++i) {
        const int row = blockIdx.x + GRID * i;
        const float4* o4 = (const float4*)(old_p  + (size_t)row * T);
        const float4* c4 = (const float4*)(curr_p + (size_t)row * T);
        #pragma unroll
        for (int cch = 2; cch < 4; ++cch) {
            const int idx = cch * 128 + tid;
            const float4 o  = __ldcs(o4 + idx);
            const float4 cc = __ldcs(c4 + idx);
            const float* ov = (const float*)&o;
            const float* cv = (const float*)&cc;
            const int combo = i * 2 + (cch - 2);
            #pragma unroll
            for (int k = 0; k < 4; ++k) {
                s_rc[(combo * 4 + k) * 128 + tid] =
                    __fdividef(cv[k], ov[k] + EPSF);
                ent = fmaf(cv[k], __logf(cv[k] + EPSF), ent);
            }
        }
    }

    // ========== Spin: wait for all arrivals, derive mean/rstd ==========
    if (tid == 0) {
        while (*(volatile int*)&g_c1 < GRID) __nanosleep(32);
        const double n    = (double)NTOT;
        const double mean = g_sum / n;
        const double var  = (g_sumsq - g_sum * g_sum / n) / (n - 1.0);  // ddof=1
        sh_mean = (float)mean;
        sh_rstd = (float)(1.0 / (sqrt(var) + (double)EPSF));
    }
    __syncthreads();
    const float mean = sh_mean, rstd = sh_rstd;

    // ========== Phase 2b: register-cached elements ==========
    #pragma unroll
    for (int i = 0; i < RPC; ++i) {
        const __half* ar = &s_adv[i][0];
        #pragma unroll
        for (int cch = 0; cch < 2; ++cch) {
            const int idx = cch * 128 + tid;
            const uint2 hh = *(const uint2*)(ar + idx * 4);
            const float2 fa = __half22float2(*(const __half2*)&hh.x);
            const float2 fb = __half22float2(*(const __half2*)&hh.y);
            const float av[4] = {fa.x, fa.y, fb.x, fb.y};
            #pragma unroll
            for (int k = 0; k < 4; ++k) {
                const float ratio = rcache[(i * 2 + cch) * 4 + k];
                const float adv   = (av[k] - mean) * rstd;
                const float rlo = fminf(ratio, 1.f + CLIPP);
                const float rhi = fmaxf(ratio, 1.f - CLIPP);
                ppo = fmaf((adv > 0.f) ? rlo : rhi, adv, ppo);
            }
        }
    }
    // smem-cached elements (rows 0..1, chunks 2..3)
    #pragma unroll
    for (int i = 0; i < 2; ++i) {
        const __half* ar = &s_adv[i][0];
        #pragma unroll
        for (int cch = 2; cch < 4; ++cch) {
            const int idx = cch * 128 + tid;
            const uint2 hh = *(const uint2*)(ar + idx * 4);
            const float2 fa = __half22float2(*(const __half2*)&hh.x);
            const float2 fb = __half22float2(*(const __half2*)&hh.y);
            const float av[4] = {fa.x, fa.y, fb.x, fb.y};
            const int combo = i * 2 + (cch - 2);
            #pragma unroll
            for (int k = 0; k < 4; ++k) {
                const float ratio = s_rc[(combo * 4 + k) * 128 + tid];
                const float adv   = (av[k] - mean) * rstd;
                const float rlo = fminf(ratio, 1.f + CLIPP);
                const float rhi = fmaxf(ratio, 1.f - CLIPP);
                ppo = fmaf((adv > 0.f) ? rlo : rhi, adv, ppo);
            }
        }
    }

    // ========== Phase 2c: remaining elements (rows 2..3, chunks 2..3) ==========
    #pragma unroll
    for (int i = 2; i < RPC; ++i) {
        const int row = blockIdx.x + GRID * i;
        const float4* o4 = (const float4*)(old_p  + (size_t)row * T);
        const float4* c4 = (const float4*)(curr_p + (size_t)row * T);
        const __half* ar = &s_adv[i][0];
        #pragma unroll
        for (int cch = 2; cch < 4; ++cch) {
            const int idx = cch * 128 + tid;
            const float4 o  = __ldcs(o4 + idx);
            const float4 cc = __ldcs(c4 + idx);
            const uint2 hh = *(const uint2*)(ar + idx * 4);
            const float2 fa = __half22float2(*(const __half2*)&hh.x);
            const float2 fb = __half22float2(*(const __half2*)&hh.y);
            const float av[4] = {fa.x, fa.y, fb.x, fb.y};
            const float* ov = (const float*)&o;
            const float* cv = (const float*)&cc;
            #pragma unroll
            for (int k = 0; k < 4; ++k) {
                const float ratio = __fdividef(cv[k], ov[k] + EPSF);
                const float adv   = (av[k] - mean) * rstd;
                const float rlo = fminf(ratio, 1.f + CLIPP);
                const float rhi = fmaxf(ratio, 1.f - CLIPP);
                ppo = fmaf((adv > 0.f) ? rlo : rhi, adv, ppo);
                ent = fmaf(cv[k], __logf(cv[k] + EPSF), ent);
            }
        }
    }

    // ========== Reduce + finalize ==========
    #pragma unroll
    for (int off = 16; off; off >>= 1) {
        ppo += __shfl_down_sync(FULL, ppo, off);
        ent += __shfl_down_sync(FULL, ent, off);
    }
    __syncthreads();   // s_a/s_b reuse
    if (lane == 0) { s_a[wid] = (double)ppo; s_b[wid] = (double)ent; }
    __syncthreads();

    if (tid == 0) {
        double bp = 0.0, be = 0.0;
        #pragma unroll
        for (int i = 0; i < 4; ++i) { bp += s_a[i]; be += s_b[i]; }
        atomicAdd(&g_ppo, bp);
        atomicAdd(&g_ent, be);
        __threadfence();
        const int done = atomicAdd(&g_c2, 1);
        if (done == GRID - 1) {
            const double n   = (double)NTOT;
            const double pl  = -(g_ppo / n);
            const double vls = 0.5  * (g_sumsq / n);   // value_loss = mean(adv^2)
            const double el  = -0.01 * (g_ent / n);
            out[0] = (float)(pl + vls + el);
            out[1] = (float)pl;
            out[2] = (float)vls;
            out[3] = (float)el;
            g_sum = 0.0; g_sumsq = 0.0; g_ppo = 0.0; g_ent = 0.0;
            g_c1 = 0; g_c2 = 0;
            __threadfence();
        }
    }
}

extern "C" void kernel_launch(void* const* d_in, const int* in_sizes, int n_in,
                              void* d_out, int out_size)
{
    // `values` has the unique size B*(T+1); everything else keeps metadata
    // order: rewards, ref_probs (unused), old_probs, curr_probs, masks.
    int vi = 1;
    for (int i = 0; i < n_in; ++i)
        if (in_sizes[i] == B * (T + 1)) { vi = i; break; }

    const float* others[8];
    int k = 0;
    for (int i = 0; i < n_in; ++i)
        if (i != vi) others[k++] = (const float*)d_in[i];

    const float* rewards = others[0];
    const float* old_p   = others[2];
    const float* curr_p  = others[3];
    const float* masks   = others[4];
    const float* values  = (const float*)d_in[vi];

    ppo_fused_kernel<<<GRID, 128>>>(rewards, values, masks, old_p, curr_p,
                                    (float*)d_out);
}